// round 4
// baseline (speedup 1.0000x reference)
#include <cuda_runtime.h>
#include <math.h>

#define NVEH 8192
#define NT   512
#define VPC  32           // vehicles per CTA
#define TPB  160          // 8 vehicle-groups x 20 units
#define NRP  16           // k row-pairs (32 rows: 12 x + 20 h)
#define XSTR 36           // smem row stride (floats), 16B aligned

typedef unsigned long long ull;

// ---------------- packed f32x2 helpers (sm_103a) ----------------
__device__ __forceinline__ ull fma2(ull a, ull b, ull c){
    ull d;
    asm("fma.rn.f32x2 %0, %1, %2, %3;" : "=l"(d) : "l"(a), "l"(b), "l"(c));
    return d;
}
__device__ __forceinline__ ull pack2(float a, float b){
    ull d; asm("mov.b64 %0, {%1, %2};" : "=l"(d) : "f"(a), "f"(b)); return d;
}
__device__ __forceinline__ float2 unpack2(ull a){
    float2 r; asm("mov.b64 {%0, %1}, %2;" : "=f"(r.x), "=f"(r.y) : "l"(a)); return r;
}

// ---------------- activations ----------------
__device__ __forceinline__ float sigm(float x){
    float e = __expf(-x);
    return __fdividef(1.0f, 1.0f + e);
}
__device__ __forceinline__ float tanh_acc(float x){
    float s = sigm(2.0f * x);
    return fmaf(2.0f, s, -1.0f);
}
__device__ __forceinline__ float nanfix(float x){
    unsigned uu = __float_as_uint(x);
    return ((uu & 0x7fffffffu) > 0x7f800000u) ? 1.0f : x;
}

__global__ __launch_bounds__(TPB, 2)
void lstm_kernel(
    const float* __restrict__ lf,   // (8192,512,12)
    const float* __restrict__ tt,   // (8192,512)
    const float* __restrict__ hs,   // (2,8192,20)
    const float* __restrict__ Wk,   // (12,80)
    const float* __restrict__ Wr,   // (20,80)
    const float* __restrict__ bl,   // (80)
    const float* __restrict__ Wd,   // (20,10)
    const float* __restrict__ bd,   // (10)
    const float* __restrict__ Wlc,  // (10,3)
    const float* __restrict__ blc,  // (3)
    float* __restrict__ out)
{
    // sX[buf][veh][0..11]=x_t, [12..31]=h_{t-1}; double buffered
    __shared__ float sX[2][VPC][XSTR];
    __shared__ ull   sWz[NRP][80];   // packed k-rowpair weights, col cp = u*4 + gate
    __shared__ ull   sWdP[10][10];   // packed h-rowpair dense weights [rp][col]
    __shared__ float sbd[10];
    __shared__ float sWlc[30];
    __shared__ float sblc[3];

    const int tid = threadIdx.x;
    const int blk = blockIdx.x;

    // ---- init shared (one time) ----
    for (int idx = tid; idx < NRP*80; idx += TPB){
        int rp = idx / 80, cp = idx % 80;
        int u = cp >> 2, gg = cp & 3;
        int oc = gg*20 + u;                 // original col (keras gate order i,f,c,o)
        int k0 = 2*rp, k1 = 2*rp + 1;
        float w0 = (k0 < 12) ? Wk[k0*80 + oc] : Wr[(k0-12)*80 + oc];
        float w1 = (k1 < 12) ? Wk[k1*80 + oc] : Wr[(k1-12)*80 + oc];
        sWz[rp][cp] = pack2(w0, w1);
    }
    for (int idx = tid; idx < 100; idx += TPB){
        int rp = idx / 10, cc = idx % 10;
        sWdP[rp][cc] = pack2(Wd[(2*rp)*10 + cc], Wd[(2*rp+1)*10 + cc]);
    }
    for (int idx = tid; idx < 10; idx += TPB) sbd[idx]  = bd[idx];
    for (int idx = tid; idx < 30; idx += TPB) sWlc[idx] = Wlc[idx];
    for (int idx = tid; idx < 3;  idx += TPB) sblc[idx] = blc[idx];
    // initial h into buf0
    for (int idx = tid; idx < VPC*20; idx += TPB){
        int v = idx / 20, k = idx % 20;
        sX[0][v][12 + k] = hs[((size_t)blk*VPC + v)*20 + k];
    }

    // ---- per-thread roles ----
    const int u  = tid % 20;         // unit
    const int g  = tid / 20;         // vehicle group (0..7), vehicles 4g..4g+3
    const int xv = tid / 3;          // x-loader: vehicle (tid<96)
    const int xc = tid - 3*xv;       // x-loader: chunk 0..2
    const int dv = tid >> 1;         // dense: vehicle (tid<64)
    const int dh = tid & 1;          // dense: col half (5 cols)

    // x(t=0) staged into buf0 by loader threads
    if (tid < 96){
        const float4 e = *reinterpret_cast<const float4*>(
            lf + ((size_t)(blk*VPC + xv) * NT + 0) * 12 + 4*xc);
        float pos = (xc < 2) ? tt[(size_t)(blk*VPC + xv) * NT + 0] : 0.0f;
        float4 xo;
        if (xc == 0){
            xo.x = (e.x - pos) * 0.01f; xo.y = (e.y - pos) * 0.01f;
            xo.z = (e.z - pos) * 0.01f; xo.w = (pos - e.w) * 0.01f;
        } else if (xc == 1){
            xo.x = (pos - e.x) * 0.01f; xo.y = (pos - e.y) * 0.01f;
            xo.z = e.z * 0.025f;        xo.w = e.w * 0.025f;
        } else {
            xo.x = e.x * 0.025f; xo.y = e.y * 0.025f;
            xo.z = e.z * 0.025f; xo.w = e.w * 0.025f;
        }
        xo.x = nanfix(xo.x); xo.y = nanfix(xo.y);
        xo.z = nanfix(xo.z); xo.w = nanfix(xo.w);
        *reinterpret_cast<float4*>(&sX[0][xv][4*xc]) = xo;
    }
    __syncthreads();

    // ---- weights into registers (64 b64) ----
    ull wreg[NRP][4];
    #pragma unroll
    for (int rp = 0; rp < NRP; rp++)
        #pragma unroll
        for (int cc = 0; cc < 4; cc++)
            wreg[rp][cc] = sWz[rp][4*u + cc];
    float bz[4];
    #pragma unroll
    for (int cc = 0; cc < 4; cc++) bz[cc] = bl[cc*20 + u];

    // ---- cell/hidden state (4 vehicles, this unit) ----
    float c4[4], h4[4];
    #pragma unroll
    for (int i = 0; i < 4; i++){
        size_t vg = (size_t)(blk*VPC + 4*g + i);
        c4[i] = hs[(size_t)NVEH*20 + vg*20 + u];
        h4[i] = hs[vg*20 + u];
    }

    const size_t LC_BASE = (size_t)NVEH * NT;
    const size_t H_BASE  = (size_t)NVEH * NT * 4;
    const size_t C_BASE  = H_BASE + (size_t)NVEH * 20;
    float* outlc = out + LC_BASE + (size_t)(blk*VPC + dv) * NT * 3;

    const float* lfx = lf + ((size_t)(blk*VPC + xv) * NT) * 12 + 4*xc;
    const float* ttx = tt + (size_t)(blk*VPC + xv) * NT;

    #pragma unroll 1
    for (int t = 0; t < NT; t++){
        const int cur = t & 1, nxt = cur ^ 1;

        // ---- prefetch x(t+1) early (hide LDG latency under compute) ----
        float4 xo;
        bool havex = (tid < 96) && (t + 1 < NT);
        if (havex){
            const float4 e = *reinterpret_cast<const float4*>(lfx + (size_t)(t+1)*12);
            float pos = (xc < 2) ? ttx[t+1] : 0.0f;
            if (xc == 0){
                xo.x = (e.x - pos) * 0.01f; xo.y = (e.y - pos) * 0.01f;
                xo.z = (e.z - pos) * 0.01f; xo.w = (pos - e.w) * 0.01f;
            } else if (xc == 1){
                xo.x = (pos - e.x) * 0.01f; xo.y = (pos - e.y) * 0.01f;
                xo.z = e.z * 0.025f;        xo.w = e.w * 0.025f;
            } else {
                xo.x = e.x * 0.025f; xo.y = e.y * 0.025f;
                xo.z = e.z * 0.025f; xo.w = e.w * 0.025f;
            }
            xo.x = nanfix(xo.x); xo.y = nanfix(xo.y);
            xo.z = nanfix(xo.z); xo.w = nanfix(xo.w);
        }

        // ---- dense(10)+relu + lc(3) for step t-1, from h(t-1) in buf[cur] ----
        if (t > 0 && tid < 64){
            const float* hrow = &sX[cur][dv][12];
            ull a2[5];
            #pragma unroll
            for (int cc = 0; cc < 5; cc++) a2[cc] = 0ULL;
            #pragma unroll
            for (int rp = 0; rp < 10; rp++){
                ull hm = *reinterpret_cast<const ull*>(hrow + 2*rp);
                #pragma unroll
                for (int cc = 0; cc < 5; cc++)
                    a2[cc] = fma2(sWdP[rp][dh*5 + cc], hm, a2[cc]);
            }
            float d5[5];
            #pragma unroll
            for (int cc = 0; cc < 5; cc++){
                float2 pr = unpack2(a2[cc]);
                d5[cc] = fmaxf(pr.x + pr.y + sbd[dh*5 + cc], 0.0f);
            }
            float dof[5];
            #pragma unroll
            for (int cc = 0; cc < 5; cc++)
                dof[cc] = __shfl_xor_sync(0xffffffffu, d5[cc], 1);
            if (dh == 0){
                #pragma unroll
                for (int o = 0; o < 3; o++){
                    float acc = sblc[o];
                    #pragma unroll
                    for (int m = 0; m < 5; m++){
                        acc = fmaf(d5[m],  sWlc[m*3 + o],     acc);
                        acc = fmaf(dof[m], sWlc[(5+m)*3 + o], acc);
                    }
                    outlc[(size_t)(t-1)*3 + o] = acc;
                }
            }
        }

        // ---- z = [x;h] @ W + b for 4 vehicles (weights in regs) ----
        #pragma unroll
        for (int i = 0; i < 4; i++){
            const float* row = sX[cur][4*g + i];
            ull z0 = pack2(bz[0], 0.0f);
            ull z1 = pack2(bz[1], 0.0f);
            ull z2 = pack2(bz[2], 0.0f);
            ull z3 = pack2(bz[3], 0.0f);
            #pragma unroll
            for (int rp = 0; rp < NRP; rp++){
                ull m2 = *reinterpret_cast<const ull*>(row + 2*rp);
                z0 = fma2(wreg[rp][0], m2, z0);
                z1 = fma2(wreg[rp][1], m2, z1);
                z2 = fma2(wreg[rp][2], m2, z2);
                z3 = fma2(wreg[rp][3], m2, z3);
            }
            float2 p0 = unpack2(z0), p1 = unpack2(z1), p2 = unpack2(z2), p3 = unpack2(z3);
            float zi = p0.x + p0.y;
            float zf = p1.x + p1.y;
            float zg = p2.x + p2.y;
            float zo = p3.x + p3.y;
            float cn = fmaf(sigm(zf), c4[i], sigm(zi) * tanh_acc(zg));
            c4[i] = cn;
            float hnew = sigm(zo) * tanh_acc(cn);
            h4[i] = hnew;
            sX[nxt][4*g + i][12 + u] = hnew;       // publish h(t)
        }

        // ---- stage x(t+1) ----
        if (havex) *reinterpret_cast<float4*>(&sX[nxt][xv][4*xc]) = xo;

        __syncthreads();
    }

    // ---- epilogue: dense/lc for t = NT-1 (h(511) is in buf[0]) ----
    if (tid < 64){
        const float* hrow = &sX[0][dv][12];
        ull a2[5];
        #pragma unroll
        for (int cc = 0; cc < 5; cc++) a2[cc] = 0ULL;
        #pragma unroll
        for (int rp = 0; rp < 10; rp++){
            ull hm = *reinterpret_cast<const ull*>(hrow + 2*rp);
            #pragma unroll
            for (int cc = 0; cc < 5; cc++)
                a2[cc] = fma2(sWdP[rp][dh*5 + cc], hm, a2[cc]);
        }
        float d5[5];
        #pragma unroll
        for (int cc = 0; cc < 5; cc++){
            float2 pr = unpack2(a2[cc]);
            d5[cc] = fmaxf(pr.x + pr.y + sbd[dh*5 + cc], 0.0f);
        }
        float dof[5];
        #pragma unroll
        for (int cc = 0; cc < 5; cc++)
            dof[cc] = __shfl_xor_sync(0xffffffffu, d5[cc], 1);
        if (dh == 0){
            #pragma unroll
            for (int o = 0; o < 3; o++){
                float acc = sblc[o];
                #pragma unroll
                for (int m = 0; m < 5; m++){
                    acc = fmaf(d5[m],  sWlc[m*3 + o],     acc);
                    acc = fmaf(dof[m], sWlc[(5+m)*3 + o], acc);
                }
                outlc[(size_t)(NT-1)*3 + o] = acc;
            }
        }
    }

    // ---- final states ----
    #pragma unroll
    for (int i = 0; i < 4; i++){
        size_t vg = (size_t)(blk*VPC + 4*g + i);
        out[H_BASE + vg*20 + u] = h4[i];
        out[C_BASE + vg*20 + u] = c4[i];
    }
}

extern "C" void kernel_launch(void* const* d_in, const int* in_sizes, int n_in,
                              void* d_out, int out_size)
{
    const float* lf  = (const float*)d_in[0];
    const float* tt  = (const float*)d_in[1];
    const float* hs  = (const float*)d_in[2];
    const float* Wk  = (const float*)d_in[3];
    const float* Wr  = (const float*)d_in[4];
    const float* bl  = (const float*)d_in[5];
    const float* Wd  = (const float*)d_in[6];
    const float* bd  = (const float*)d_in[7];
    const float* Wlc = (const float*)d_in[8];
    const float* blc = (const float*)d_in[9];
    float* out = (float*)d_out;

    cudaMemcpyAsync(out, tt, (size_t)NVEH * NT * sizeof(float),
                    cudaMemcpyDeviceToDevice);

    lstm_kernel<<<NVEH / VPC, TPB>>>(lf, tt, hs, Wk, Wr, bl, Wd, bd, Wlc, blc, out);
}

// round 5
// speedup vs baseline: 1.1211x; 1.1211x over previous
#include <cuda_runtime.h>
#include <math.h>

#define NVEH 8192
#define NT   512
#define VPC  28           // vehicles per CTA
#define TPB  140          // 7 groups x 20 units
#define NGRP 7
#define NRP  16           // k row-pairs (32 rows: 12 x + 20 h)
#define XSTR 36           // smem row stride (floats), 16B aligned
#define GRID ((NVEH + VPC - 1) / VPC)   // 293

typedef unsigned long long ull;

// ---------------- packed f32x2 helpers (sm_103a) ----------------
__device__ __forceinline__ ull fma2(ull a, ull b, ull c){
    ull d;
    asm("fma.rn.f32x2 %0, %1, %2, %3;" : "=l"(d) : "l"(a), "l"(b), "l"(c));
    return d;
}
__device__ __forceinline__ ull pack2(float a, float b){
    ull d; asm("mov.b64 %0, {%1, %2};" : "=l"(d) : "f"(a), "f"(b)); return d;
}
__device__ __forceinline__ float2 unpack2(ull a){
    float2 r; asm("mov.b64 {%0, %1}, %2;" : "=f"(r.x), "=f"(r.y) : "l"(a)); return r;
}

// ---------------- activations: single-MUFU tanh ----------------
__device__ __forceinline__ float tanh_f(float x){
    float y; asm("tanh.approx.f32 %0, %1;" : "=f"(y) : "f"(x)); return y;
}
__device__ __forceinline__ float sigt(float x){
    return fmaf(0.5f, tanh_f(0.5f * x), 0.5f);
}
__device__ __forceinline__ float nanfix(float x){
    unsigned uu = __float_as_uint(x);
    return ((uu & 0x7fffffffu) > 0x7f800000u) ? 1.0f : x;
}

__global__ __launch_bounds__(TPB, 2)
void lstm_kernel(
    const float* __restrict__ lf,   // (8192,512,12)
    const float* __restrict__ tt,   // (8192,512)
    const float* __restrict__ hs,   // (2,8192,20)
    const float* __restrict__ Wk,   // (12,80)
    const float* __restrict__ Wr,   // (20,80)
    const float* __restrict__ bl,   // (80)
    const float* __restrict__ Wd,   // (20,10)
    const float* __restrict__ bd,   // (10)
    const float* __restrict__ Wlc,  // (10,3)
    const float* __restrict__ blc,  // (3)
    float* __restrict__ out)
{
    __shared__ float sX[2][VPC][XSTR];   // [0..11]=x_t, [12..31]=h_{t-1}
    __shared__ ull   sWz[NRP][80];       // packed k-rowpair weights, col cp = u*4 + gate
    __shared__ ull   sWdP[10][10];       // packed dense weights [rowpair][col]
    __shared__ float sbd[10];
    __shared__ float sWlc[30];
    __shared__ float sblc[3];

    const int tid = threadIdx.x;
    const int blk = blockIdx.x;
    const int vb  = blk * VPC;

    // ---- zero dynamic smem rows (covers invalid vehicles in last CTA) ----
    for (int idx = tid; idx < 2*VPC*XSTR; idx += TPB)
        (&sX[0][0][0])[idx] = 0.0f;

    // ---- one-time shared init ----
    for (int idx = tid; idx < NRP*80; idx += TPB){
        int rp = idx / 80, cp = idx % 80;
        int u = cp >> 2, gg = cp & 3;
        int oc = gg*20 + u;                 // keras gate order i,f,c,o
        int k0 = 2*rp, k1 = 2*rp + 1;
        float w0 = (k0 < 12) ? Wk[k0*80 + oc] : Wr[(k0-12)*80 + oc];
        float w1 = (k1 < 12) ? Wk[k1*80 + oc] : Wr[(k1-12)*80 + oc];
        sWz[rp][cp] = pack2(w0, w1);
    }
    for (int idx = tid; idx < 100; idx += TPB){
        int rp = idx / 10, cc = idx % 10;
        sWdP[rp][cc] = pack2(Wd[(2*rp)*10 + cc], Wd[(2*rp+1)*10 + cc]);
    }
    for (int idx = tid; idx < 10; idx += TPB) sbd[idx]  = bd[idx];
    for (int idx = tid; idx < 30; idx += TPB) sWlc[idx] = Wlc[idx];
    for (int idx = tid; idx < 3;  idx += TPB) sblc[idx] = blc[idx];
    // initial h into buf0 (guarded)
    for (int idx = tid; idx < VPC*20; idx += TPB){
        int v = idx / 20, k = idx % 20;
        if (vb + v < NVEH)
            sX[0][v][12 + k] = hs[((size_t)(vb + v))*20 + k];
    }

    // ---- per-thread roles ----
    const int u  = tid % 20;         // unit
    const int g  = tid / 20;         // vehicle group (0..6), vehicles 4g..4g+3
    const int xv = tid / 3;          // x-loader: vehicle (tid<84)
    const int xc = tid - 3*xv;       // x-loader: chunk 0..2
    const int dt = tid - (TPB - 2*VPC);   // dense: tid>=84
    const int dv = (dt >= 0) ? (dt >> 1) : 0;
    const int dh = dt & 1;
    const bool is_loader = (tid < 3*VPC);
    const bool is_dense  = (dt >= 0);
    const bool lvalid = is_loader && (vb + xv < NVEH);
    const bool dvalid = is_dense  && (vb + dv < NVEH);

    // x(t=0) staged into buf0 by loader threads
    if (lvalid){
        const float4 e = *reinterpret_cast<const float4*>(
            lf + ((size_t)(vb + xv) * NT) * 12 + 4*xc);
        float pos = (xc < 2) ? tt[(size_t)(vb + xv) * NT] : 0.0f;
        float4 xo;
        if (xc == 0){
            xo.x = (e.x - pos) * 0.01f; xo.y = (e.y - pos) * 0.01f;
            xo.z = (e.z - pos) * 0.01f; xo.w = (pos - e.w) * 0.01f;
        } else if (xc == 1){
            xo.x = (pos - e.x) * 0.01f; xo.y = (pos - e.y) * 0.01f;
            xo.z = e.z * 0.025f;        xo.w = e.w * 0.025f;
        } else {
            xo.x = e.x * 0.025f; xo.y = e.y * 0.025f;
            xo.z = e.z * 0.025f; xo.w = e.w * 0.025f;
        }
        xo.x = nanfix(xo.x); xo.y = nanfix(xo.y);
        xo.z = nanfix(xo.z); xo.w = nanfix(xo.w);
        *reinterpret_cast<float4*>(&sX[0][xv][4*xc]) = xo;
    }
    __syncthreads();

    // ---- z weights into registers (64 b64) ----
    ull wreg[NRP][4];
    #pragma unroll
    for (int rp = 0; rp < NRP; rp++)
        #pragma unroll
        for (int cc = 0; cc < 4; cc++)
            wreg[rp][cc] = sWz[rp][4*u + cc];
    ull bzq[4];
    #pragma unroll
    for (int cc = 0; cc < 4; cc++) bzq[cc] = pack2(bl[cc*20 + u], 0.0f);

    // ---- cell/hidden state (4 vehicles, this unit) ----
    float c4[4], h4[4];
    bool zval[4];
    #pragma unroll
    for (int i = 0; i < 4; i++){
        int v = vb + 4*g + i;
        zval[i] = (v < NVEH);
        c4[i] = zval[i] ? hs[(size_t)NVEH*20 + (size_t)v*20 + u] : 0.0f;
        h4[i] = zval[i] ? hs[(size_t)v*20 + u] : 0.0f;
    }

    const size_t LC_BASE = (size_t)NVEH * NT;
    const size_t H_BASE  = (size_t)NVEH * NT * 4;
    const size_t C_BASE  = H_BASE + (size_t)NVEH * 20;
    float* outlc = out + LC_BASE + (size_t)(vb + dv) * NT * 3;

    const float* lfx = lf + ((size_t)(vb + (lvalid ? xv : 0)) * NT) * 12 + 4*xc;
    const float* ttx = tt + (size_t)(vb + (lvalid ? xv : 0)) * NT;

    #pragma unroll 1
    for (int t = 0; t < NT; t++){
        const int cur = t & 1, nxt = cur ^ 1;

        // ---- prefetch x(t+1) early (warps 0-2) ----
        float4 xo;
        const bool havex = lvalid && (t + 1 < NT);
        if (havex){
            const float4 e = *reinterpret_cast<const float4*>(lfx + (size_t)(t+1)*12);
            float pos = (xc < 2) ? ttx[t+1] : 0.0f;
            if (xc == 0){
                xo.x = (e.x - pos) * 0.01f; xo.y = (e.y - pos) * 0.01f;
                xo.z = (e.z - pos) * 0.01f; xo.w = (pos - e.w) * 0.01f;
            } else if (xc == 1){
                xo.x = (pos - e.x) * 0.01f; xo.y = (pos - e.y) * 0.01f;
                xo.z = e.z * 0.025f;        xo.w = e.w * 0.025f;
            } else {
                xo.x = e.x * 0.025f; xo.y = e.y * 0.025f;
                xo.z = e.z * 0.025f; xo.w = e.w * 0.025f;
            }
            xo.x = nanfix(xo.x); xo.y = nanfix(xo.y);
            xo.z = nanfix(xo.z); xo.w = nanfix(xo.w);
        }

        // ---- dense(10)+relu + lc(3) for step t-1 (warps 2-4) ----
        if (t > 0 && is_dense){
            const ull* hp = reinterpret_cast<const ull*>(&sX[cur][dv][12]);
            ull a2[5];
            #pragma unroll
            for (int cc = 0; cc < 5; cc++) a2[cc] = 0ULL;
            #pragma unroll
            for (int rp = 0; rp < 10; rp++){
                ull hm = hp[rp];
                #pragma unroll
                for (int cc = 0; cc < 5; cc++)
                    a2[cc] = fma2(sWdP[rp][dh*5 + cc], hm, a2[cc]);
            }
            float d5[5];
            #pragma unroll
            for (int cc = 0; cc < 5; cc++){
                float2 pr = unpack2(a2[cc]);
                d5[cc] = fmaxf(pr.x + pr.y + sbd[dh*5 + cc], 0.0f);
            }
            unsigned msk = __activemask();
            float dof[5];
            #pragma unroll
            for (int cc = 0; cc < 5; cc++)
                dof[cc] = __shfl_xor_sync(msk, d5[cc], 1);
            if (dh == 0 && dvalid){
                #pragma unroll
                for (int o = 0; o < 3; o++){
                    float acc = sblc[o];
                    #pragma unroll
                    for (int m = 0; m < 5; m++){
                        acc = fmaf(d5[m],  sWlc[m*3 + o],     acc);
                        acc = fmaf(dof[m], sWlc[(5+m)*3 + o], acc);
                    }
                    outlc[(size_t)(t-1)*3 + o] = acc;
                }
            }
        }

        // ---- z = [x;h] @ W + b for 4 vehicles (weights in regs) ----
        #pragma unroll
        for (int i = 0; i < 4; i++){
            const ulonglong2* row = reinterpret_cast<const ulonglong2*>(sX[cur][4*g + i]);
            ull z0 = bzq[0], z1 = bzq[1], z2 = bzq[2], z3 = bzq[3];
            #pragma unroll
            for (int j = 0; j < 8; j++){
                ulonglong2 mm = row[j];             // LDS.128: rows 4j..4j+3
                z0 = fma2(wreg[2*j][0],   mm.x, z0);
                z1 = fma2(wreg[2*j][1],   mm.x, z1);
                z2 = fma2(wreg[2*j][2],   mm.x, z2);
                z3 = fma2(wreg[2*j][3],   mm.x, z3);
                z0 = fma2(wreg[2*j+1][0], mm.y, z0);
                z1 = fma2(wreg[2*j+1][1], mm.y, z1);
                z2 = fma2(wreg[2*j+1][2], mm.y, z2);
                z3 = fma2(wreg[2*j+1][3], mm.y, z3);
            }
            float2 p0 = unpack2(z0), p1 = unpack2(z1), p2 = unpack2(z2), p3 = unpack2(z3);
            float ai = sigt(p0.x + p0.y);
            float af = sigt(p1.x + p1.y);
            float ag = tanh_f(p2.x + p2.y);
            float ao = sigt(p3.x + p3.y);
            float cn = fmaf(af, c4[i], ai * ag);
            c4[i] = cn;
            float hnew = ao * tanh_f(cn);
            h4[i] = hnew;
            sX[nxt][4*g + i][12 + u] = hnew;       // publish h(t)
        }

        // ---- stage x(t+1) ----
        if (havex) *reinterpret_cast<float4*>(&sX[nxt][xv][4*xc]) = xo;

        __syncthreads();
    }

    // ---- epilogue: dense/lc for t = NT-1 (h(511) in buf[0]) ----
    if (is_dense){
        const ull* hp = reinterpret_cast<const ull*>(&sX[0][dv][12]);
        ull a2[5];
        #pragma unroll
        for (int cc = 0; cc < 5; cc++) a2[cc] = 0ULL;
        #pragma unroll
        for (int rp = 0; rp < 10; rp++){
            ull hm = hp[rp];
            #pragma unroll
            for (int cc = 0; cc < 5; cc++)
                a2[cc] = fma2(sWdP[rp][dh*5 + cc], hm, a2[cc]);
        }
        float d5[5];
        #pragma unroll
        for (int cc = 0; cc < 5; cc++){
            float2 pr = unpack2(a2[cc]);
            d5[cc] = fmaxf(pr.x + pr.y + sbd[dh*5 + cc], 0.0f);
        }
        unsigned msk = __activemask();
        float dof[5];
        #pragma unroll
        for (int cc = 0; cc < 5; cc++)
            dof[cc] = __shfl_xor_sync(msk, d5[cc], 1);
        if (dh == 0 && dvalid){
            #pragma unroll
            for (int o = 0; o < 3; o++){
                float acc = sblc[o];
                #pragma unroll
                for (int m = 0; m < 5; m++){
                    acc = fmaf(d5[m],  sWlc[m*3 + o],     acc);
                    acc = fmaf(dof[m], sWlc[(5+m)*3 + o], acc);
                }
                outlc[(size_t)(NT-1)*3 + o] = acc;
            }
        }
    }

    // ---- final states ----
    #pragma unroll
    for (int i = 0; i < 4; i++){
        if (zval[i]){
            size_t v = (size_t)(vb + 4*g + i);
            out[H_BASE + v*20 + u] = h4[i];
            out[C_BASE + v*20 + u] = c4[i];
        }
    }
}

extern "C" void kernel_launch(void* const* d_in, const int* in_sizes, int n_in,
                              void* d_out, int out_size)
{
    const float* lf  = (const float*)d_in[0];
    const float* tt  = (const float*)d_in[1];
    const float* hs  = (const float*)d_in[2];
    const float* Wk  = (const float*)d_in[3];
    const float* Wr  = (const float*)d_in[4];
    const float* bl  = (const float*)d_in[5];
    const float* Wd  = (const float*)d_in[6];
    const float* bd  = (const float*)d_in[7];
    const float* Wlc = (const float*)d_in[8];
    const float* blc = (const float*)d_in[9];
    float* out = (float*)d_out;

    cudaMemcpyAsync(out, tt, (size_t)NVEH * NT * sizeof(float),
                    cudaMemcpyDeviceToDevice);

    lstm_kernel<<<GRID, TPB>>>(lf, tt, hs, Wk, Wr, bl, Wd, bd, Wlc, blc, out);
}

// round 6
// speedup vs baseline: 1.2227x; 1.0906x over previous
#include <cuda_runtime.h>
#include <math.h>

#define NVEH 8192
#define NT   512
#define VPC  32           // vehicles per CTA
#define TPB  320          // (20 units x 8 groups) x 2 k-halves
#define XSTR 36           // smem row stride (floats), 16B aligned
#define GRID (NVEH / VPC) // 256

typedef unsigned long long ull;

// ---------------- packed f32x2 helpers (sm_103a) ----------------
__device__ __forceinline__ ull fma2(ull a, ull b, ull c){
    ull d;
    asm("fma.rn.f32x2 %0, %1, %2, %3;" : "=l"(d) : "l"(a), "l"(b), "l"(c));
    return d;
}
__device__ __forceinline__ ull pack2(float a, float b){
    ull d; asm("mov.b64 %0, {%1, %2};" : "=l"(d) : "f"(a), "f"(b)); return d;
}
__device__ __forceinline__ float2 unpack2(ull a){
    float2 r; asm("mov.b64 {%0, %1}, %2;" : "=f"(r.x), "=f"(r.y) : "l"(a)); return r;
}
__device__ __forceinline__ float hadd2(ull a){
    float2 r = unpack2(a); return r.x + r.y;
}

// ---------------- activations: single-MUFU tanh ----------------
__device__ __forceinline__ float tanh_f(float x){
    float y; asm("tanh.approx.f32 %0, %1;" : "=f"(y) : "f"(x)); return y;
}
__device__ __forceinline__ float sigt(float x){
    return fmaf(0.5f, tanh_f(0.5f * x), 0.5f);
}
__device__ __forceinline__ float nanfix(float x){
    unsigned uu = __float_as_uint(x);
    return ((uu & 0x7fffffffu) > 0x7f800000u) ? 1.0f : x;
}

__global__ __launch_bounds__(TPB, 2)
void lstm_kernel(
    const float* __restrict__ lf,   // (8192,512,12)
    const float* __restrict__ tt,   // (8192,512)
    const float* __restrict__ hs,   // (2,8192,20)
    const float* __restrict__ Wk,   // (12,80)
    const float* __restrict__ Wr,   // (20,80)
    const float* __restrict__ bl,   // (80)
    const float* __restrict__ Wd,   // (20,10)
    const float* __restrict__ bd,   // (10)
    const float* __restrict__ Wlc,  // (10,3)
    const float* __restrict__ blc,  // (3)
    float* __restrict__ out)
{
    __shared__ float sX[2][VPC][XSTR];   // [0..11]=x_t, [12..31]=h_{t-1}
    __shared__ ull   sWz[16][80];        // packed k-rowpair weights, col cp = u*4 + gate
    __shared__ ull   sWdP[10][10];       // packed dense weights [rowpair][col]
    __shared__ float sbd[10];
    __shared__ float sWlc[30];
    __shared__ float sblc[3];

    const int tid = threadIdx.x;
    const int blk = blockIdx.x;
    const int vb  = blk * VPC;

    // ---- one-time shared init ----
    for (int idx = tid; idx < 16*80; idx += TPB){
        int rp = idx / 80, cp = idx % 80;
        int uu = cp >> 2, gg = cp & 3;
        int oc = gg*20 + uu;                // keras gate order i,f,c,o
        int k0 = 2*rp, k1 = 2*rp + 1;
        float w0 = (k0 < 12) ? Wk[k0*80 + oc] : Wr[(k0-12)*80 + oc];
        float w1 = (k1 < 12) ? Wk[k1*80 + oc] : Wr[(k1-12)*80 + oc];
        sWz[rp][cp] = pack2(w0, w1);
    }
    for (int idx = tid; idx < 100; idx += TPB){
        int rp = idx / 10, cc = idx % 10;
        sWdP[rp][cc] = pack2(Wd[(2*rp)*10 + cc], Wd[(2*rp+1)*10 + cc]);
    }
    for (int idx = tid; idx < 10; idx += TPB) sbd[idx]  = bd[idx];
    for (int idx = tid; idx < 30; idx += TPB) sWlc[idx] = Wlc[idx];
    for (int idx = tid; idx < 3;  idx += TPB) sblc[idx] = blc[idx];
    // initial h into buf0
    for (int idx = tid; idx < VPC*20; idx += TPB){
        int v = idx / 20, k = idx % 20;
        sX[0][v][12 + k] = hs[((size_t)(vb + v))*20 + k];
    }

    // ---- per-thread identities ----
    const int half = tid & 1;        // k-half: 0 -> rows 0..15, 1 -> rows 16..31
    const int s    = tid >> 1;       // slot 0..159
    const int u    = s % 20;         // unit
    const int g    = s / 20;         // vehicle group (0..7), vehicles 4g..4g+3
    // loaders: warps 0-2
    const int  xv = tid / 3, xc = tid - 3*xv;
    const bool is_loader = (tid < 96);
    // dense: warps 3-4
    const int  dt = tid - 96;
    const int  dv = dt >> 1, dh = dt & 1;
    const bool is_dense = (dt >= 0 && dt < 64);

    // x(t=0) staged into buf0
    if (is_loader){
        const float4 e = *reinterpret_cast<const float4*>(
            lf + ((size_t)(vb + xv) * NT) * 12 + 4*xc);
        float pos = (xc < 2) ? tt[(size_t)(vb + xv) * NT] : 0.0f;
        float4 xo;
        if (xc == 0){
            xo.x = (e.x - pos) * 0.01f; xo.y = (e.y - pos) * 0.01f;
            xo.z = (e.z - pos) * 0.01f; xo.w = (pos - e.w) * 0.01f;
        } else if (xc == 1){
            xo.x = (pos - e.x) * 0.01f; xo.y = (pos - e.y) * 0.01f;
            xo.z = e.z * 0.025f;        xo.w = e.w * 0.025f;
        } else {
            xo.x = e.x * 0.025f; xo.y = e.y * 0.025f;
            xo.z = e.z * 0.025f; xo.w = e.w * 0.025f;
        }
        xo.x = nanfix(xo.x); xo.y = nanfix(xo.y);
        xo.z = nanfix(xo.z); xo.w = nanfix(xo.w);
        *reinterpret_cast<float4*>(&sX[0][xv][4*xc]) = xo;
    }
    __syncthreads();

    // ---- this thread's half of the z weights (32 b64) ----
    ull wreg[8][4];
    #pragma unroll
    for (int rp = 0; rp < 8; rp++)
        #pragma unroll
        for (int cc = 0; cc < 4; cc++)
            wreg[rp][cc] = sWz[half*8 + rp][4*u + cc];
    // bias carried by half 0 only
    ull bzq[4];
    #pragma unroll
    for (int cc = 0; cc < 4; cc++)
        bzq[cc] = half ? 0ULL : pack2(bl[cc*20 + u], 0.0f);

    // owned vehicles: 4g + 2p + half, p in {0,1}
    float c2[2];
    #pragma unroll
    for (int p = 0; p < 2; p++)
        c2[p] = hs[(size_t)NVEH*20 + (size_t)(vb + 4*g + 2*p + half)*20 + u];

    const size_t LC_BASE = (size_t)NVEH * NT;
    const size_t H_BASE  = (size_t)NVEH * NT * 4;
    const size_t C_BASE  = H_BASE + (size_t)NVEH * 20;

    const float* lfx = lf + ((size_t)(vb + xv) * NT) * 12 + 4*xc;
    const float* ttx = tt + (size_t)(vb + xv) * NT;
    float* outlc = out + LC_BASE + (size_t)(vb + dv) * NT * 3;

    #pragma unroll 1
    for (int t = 0; t < NT; t++){
        const int cur = t & 1, nxt = cur ^ 1;

        // ---- loaders: fetch + transform x(t+1) ----
        float4 xo;
        const bool havex = is_loader && (t + 1 < NT);
        if (havex){
            const float4 e = *reinterpret_cast<const float4*>(lfx + (size_t)(t+1)*12);
            float pos = (xc < 2) ? ttx[t+1] : 0.0f;
            if (xc == 0){
                xo.x = (e.x - pos) * 0.01f; xo.y = (e.y - pos) * 0.01f;
                xo.z = (e.z - pos) * 0.01f; xo.w = (pos - e.w) * 0.01f;
            } else if (xc == 1){
                xo.x = (pos - e.x) * 0.01f; xo.y = (pos - e.y) * 0.01f;
                xo.z = e.z * 0.025f;        xo.w = e.w * 0.025f;
            } else {
                xo.x = e.x * 0.025f; xo.y = e.y * 0.025f;
                xo.z = e.z * 0.025f; xo.w = e.w * 0.025f;
            }
            xo.x = nanfix(xo.x); xo.y = nanfix(xo.y);
            xo.z = nanfix(xo.z); xo.w = nanfix(xo.w);
        }

        // ---- dense(10)+relu + lc(3) for step t-1 (warps 3-4) ----
        if (t > 0 && is_dense){
            const ull* hp = reinterpret_cast<const ull*>(&sX[cur][dv][12]);
            ull a2[5];
            #pragma unroll
            for (int cc = 0; cc < 5; cc++) a2[cc] = 0ULL;
            #pragma unroll
            for (int rp = 0; rp < 10; rp++){
                ull hm = hp[rp];
                #pragma unroll
                for (int cc = 0; cc < 5; cc++)
                    a2[cc] = fma2(sWdP[rp][dh*5 + cc], hm, a2[cc]);
            }
            float d5[5];
            #pragma unroll
            for (int cc = 0; cc < 5; cc++)
                d5[cc] = fmaxf(hadd2(a2[cc]) + sbd[dh*5 + cc], 0.0f);
            unsigned msk = __activemask();
            float dof[5];
            #pragma unroll
            for (int cc = 0; cc < 5; cc++)
                dof[cc] = __shfl_xor_sync(msk, d5[cc], 1);
            if (dh == 0){
                #pragma unroll
                for (int o = 0; o < 3; o++){
                    float acc = sblc[o];
                    #pragma unroll
                    for (int m = 0; m < 5; m++){
                        acc = fmaf(d5[m],  sWlc[m*3 + o],     acc);
                        acc = fmaf(dof[m], sWlc[(5+m)*3 + o], acc);
                    }
                    outlc[(size_t)(t-1)*3 + o] = acc;
                }
            }
        }

        // ---- z for 4 vehicles in 2 passes of 2; k-split halves + shfl combine ----
        #pragma unroll
        for (int p = 0; p < 2; p++){
            const int v0 = 4*g + 2*p;
            const ulonglong2* r0 = reinterpret_cast<const ulonglong2*>(&sX[cur][v0][half*16]);
            const ulonglong2* r1 = reinterpret_cast<const ulonglong2*>(&sX[cur][v0+1][half*16]);
            ull a0 = bzq[0], a1 = bzq[1], a2q = bzq[2], a3 = bzq[3];   // veh v0
            ull b0 = bzq[0], b1 = bzq[1], b2q = bzq[2], b3 = bzq[3];   // veh v0+1
            #pragma unroll
            for (int jj = 0; jj < 4; jj++){
                ulonglong2 m0 = r0[jj];
                ulonglong2 m1 = r1[jj];
                a0  = fma2(wreg[2*jj][0],   m0.x, a0);
                a1  = fma2(wreg[2*jj][1],   m0.x, a1);
                a2q = fma2(wreg[2*jj][2],   m0.x, a2q);
                a3  = fma2(wreg[2*jj][3],   m0.x, a3);
                a0  = fma2(wreg[2*jj+1][0], m0.y, a0);
                a1  = fma2(wreg[2*jj+1][1], m0.y, a1);
                a2q = fma2(wreg[2*jj+1][2], m0.y, a2q);
                a3  = fma2(wreg[2*jj+1][3], m0.y, a3);
                b0  = fma2(wreg[2*jj][0],   m1.x, b0);
                b1  = fma2(wreg[2*jj][1],   m1.x, b1);
                b2q = fma2(wreg[2*jj][2],   m1.x, b2q);
                b3  = fma2(wreg[2*jj][3],   m1.x, b3);
                b0  = fma2(wreg[2*jj+1][0], m1.y, b0);
                b1  = fma2(wreg[2*jj+1][1], m1.y, b1);
                b2q = fma2(wreg[2*jj+1][2], m1.y, b2q);
                b3  = fma2(wreg[2*jj+1][3], m1.y, b3);
            }
            float za[4] = { hadd2(a0), hadd2(a1), hadd2(a2q), hadd2(a3) };
            float zb[4] = { hadd2(b0), hadd2(b1), hadd2(b2q), hadd2(b3) };
            // this lane owns veh v0+half; partner partials arrive via shfl_xor(1)
            float zfull[4];
            #pragma unroll
            for (int cc = 0; cc < 4; cc++){
                float mine = half ? zb[cc] : za[cc];
                float send = half ? za[cc] : zb[cc];
                zfull[cc] = mine + __shfl_xor_sync(0xffffffffu, send, 1);
            }
            float ai = sigt(zfull[0]);
            float af = sigt(zfull[1]);
            float ag = tanh_f(zfull[2]);
            float ao = sigt(zfull[3]);
            float cn = fmaf(af, c2[p], ai * ag);
            c2[p] = cn;
            float hv = ao * tanh_f(cn);
            sX[nxt][v0 + half][12 + u] = hv;       // publish h(t)
        }

        // ---- stage x(t+1) ----
        if (havex) *reinterpret_cast<float4*>(&sX[nxt][xv][4*xc]) = xo;

        __syncthreads();
    }

    // ---- epilogue: dense/lc for t = NT-1 (h(511) is in buf[0], NT even) ----
    if (is_dense){
        const ull* hp = reinterpret_cast<const ull*>(&sX[0][dv][12]);
        ull a2[5];
        #pragma unroll
        for (int cc = 0; cc < 5; cc++) a2[cc] = 0ULL;
        #pragma unroll
        for (int rp = 0; rp < 10; rp++){
            ull hm = hp[rp];
            #pragma unroll
            for (int cc = 0; cc < 5; cc++)
                a2[cc] = fma2(sWdP[rp][dh*5 + cc], hm, a2[cc]);
        }
        float d5[5];
        #pragma unroll
        for (int cc = 0; cc < 5; cc++)
            d5[cc] = fmaxf(hadd2(a2[cc]) + sbd[dh*5 + cc], 0.0f);
        unsigned msk = __activemask();
        float dof[5];
        #pragma unroll
        for (int cc = 0; cc < 5; cc++)
            dof[cc] = __shfl_xor_sync(msk, d5[cc], 1);
        if (dh == 0){
            #pragma unroll
            for (int o = 0; o < 3; o++){
                float acc = sblc[o];
                #pragma unroll
                for (int m = 0; m < 5; m++){
                    acc = fmaf(d5[m],  sWlc[m*3 + o],     acc);
                    acc = fmaf(dof[m], sWlc[(5+m)*3 + o], acc);
                }
                outlc[(size_t)(NT-1)*3 + o] = acc;
            }
        }
    }

    // ---- final states: owned vehicles 4g+half, 4g+2+half ----
    #pragma unroll
    for (int p = 0; p < 2; p++){
        size_t v = (size_t)(vb + 4*g + 2*p + half);
        out[H_BASE + v*20 + u] = sX[0][4*g + 2*p + half][12 + u];
        out[C_BASE + v*20 + u] = c2[p];
    }
}

extern "C" void kernel_launch(void* const* d_in, const int* in_sizes, int n_in,
                              void* d_out, int out_size)
{
    const float* lf  = (const float*)d_in[0];
    const float* tt  = (const float*)d_in[1];
    const float* hs  = (const float*)d_in[2];
    const float* Wk  = (const float*)d_in[3];
    const float* Wr  = (const float*)d_in[4];
    const float* bl  = (const float*)d_in[5];
    const float* Wd  = (const float*)d_in[6];
    const float* bd  = (const float*)d_in[7];
    const float* Wlc = (const float*)d_in[8];
    const float* blc = (const float*)d_in[9];
    float* out = (float*)d_out;

    cudaMemcpyAsync(out, tt, (size_t)NVEH * NT * sizeof(float),
                    cudaMemcpyDeviceToDevice);

    lstm_kernel<<<GRID, TPB>>>(lf, tt, hs, Wk, Wr, bl, Wd, bd, Wlc, blc, out);
}